// round 15
// baseline (speedup 1.0000x reference)
#include <cuda_runtime.h>
#include <cuda_bf16.h>
#include <math.h>

#define MAX_NODES 50000
#define D 16
#define NTYPES 16
#define SRP 20   // smem row pitch in floats: 80B, 16B-aligned, conflict-free row split

// Scratch (allocation-free rule: __device__ globals)
__device__ int   g_cnt_out[MAX_NODES * NTYPES]; // out-edge type counts
__device__ int   g_cnt_in [MAX_NODES * NTYPES]; // in-edge type counts
__device__ int   g_pos[NTYPES];                 // bucket fill counters -> final counts
// Type-sorted self-contained node records: [x_norm[16], cf[16]] = 128 B each
__device__ float g_rec[(size_t)NTYPES * MAX_NODES * 32];

// ---------------------------------------------------------------- K0: zero counters + out
__global__ void k_zero(float* out) {
    int i = blockIdx.x * blockDim.x + threadIdx.x;
    int total4 = (MAX_NODES * NTYPES) / 4;
    if (i < total4) {
        reinterpret_cast<int4*>(g_cnt_out)[i] = make_int4(0, 0, 0, 0);
        reinterpret_cast<int4*>(g_cnt_in )[i] = make_int4(0, 0, 0, 0);
    }
    if (i < NTYPES) g_pos[i] = 0;
    if (i == 0) out[0] = 0.0f;
}

// ---------------------------------------------------------------- K1: per-edge type counts (2 atomics/edge)
__global__ void __launch_bounds__(256)
k_count(const int* __restrict__ src, const int* __restrict__ dst,
        const int* __restrict__ types, int n_edges) {
    int e = blockIdx.x * blockDim.x + threadIdx.x;
    if (e >= n_edges) return;
    int s  = src[e];
    int d  = dst[e];
    int ts = __ldg(types + s);
    int td = __ldg(types + d);
    atomicAdd(&g_cnt_out[s * NTYPES + td], 1);
    atomicAdd(&g_cnt_in [d * NTYPES + ts], 1);
}

// ---------------------------------------------------------------- K2: build type-sorted node records (128B each)
__global__ void __launch_bounds__(256)
k_prep(const float* __restrict__ reps, const int* __restrict__ types, int n_nodes) {
    __shared__ int s_hist[NTYPES], s_base[NTYPES];

    int tid  = threadIdx.x;
    int base = blockIdx.x * 256;
    int v    = base + tid;

    if (tid < NTYPES) s_hist[tid] = 0;
    __syncthreads();

    int t = 0, lrank = 0;
    float4 cf0, cf1, cf2, cf3;
    float inv = 0.0f;
    if (v < n_nodes) {
        t = __ldg(types + v);
        lrank = atomicAdd(&s_hist[t], 1);     // smem atomic
        const int4* co = reinterpret_cast<const int4*>(g_cnt_out + v * NTYPES);
        const int4* ci = reinterpret_cast<const int4*>(g_cnt_in  + v * NTYPES);
        int4 o0 = co[0], o1 = co[1], o2 = co[2], o3 = co[3];
        int4 i0 = ci[0], i1 = ci[1], i2 = ci[2], i3 = ci[3];
        int deg = i0.x+i0.y+i0.z+i0.w + i1.x+i1.y+i1.z+i1.w
                + i2.x+i2.y+i2.z+i2.w + i3.x+i3.y+i3.z+i3.w;
        inv = (deg > 0) ? rsqrtf((float)deg) : 0.0f;
        cf0 = make_float4((float)(o0.x-i0.x), (float)(o0.y-i0.y), (float)(o0.z-i0.z), (float)(o0.w-i0.w));
        cf1 = make_float4((float)(o1.x-i1.x), (float)(o1.y-i1.y), (float)(o1.z-i1.z), (float)(o1.w-i1.w));
        cf2 = make_float4((float)(o2.x-i2.x), (float)(o2.y-i2.y), (float)(o2.z-i2.z), (float)(o2.w-i2.w));
        cf3 = make_float4((float)(o3.x-i3.x), (float)(o3.y-i3.y), (float)(o3.z-i3.z), (float)(o3.w-i3.w));
    }
    __syncthreads();
    if (tid < NTYPES) s_base[tid] = atomicAdd(&g_pos[tid], s_hist[tid]);
    __syncthreads();

    if (v < n_nodes) {
        float x[D];
        #pragma unroll
        for (int i = 0; i < D; i++)
            x[i] = __ldg(reps + i * n_nodes + v) * inv;   // coalesced across warp

        int slot = s_base[t] + lrank;
        float4* rec = reinterpret_cast<float4*>(
            g_rec + ((size_t)t * MAX_NODES + slot) * 32);
        rec[0] = make_float4(x[0],  x[1],  x[2],  x[3]);
        rec[1] = make_float4(x[4],  x[5],  x[6],  x[7]);
        rec[2] = make_float4(x[8],  x[9],  x[10], x[11]);
        rec[3] = make_float4(x[12], x[13], x[14], x[15]);
        rec[4] = cf0; rec[5] = cf1; rec[6] = cf2; rec[7] = cf3;
    }
}

// ---------------------------------------------------------------- K3: weighted matvec + sum of squares
// Block = (type, tile of 64 nodes); thread = (node, rq) computes rows
// {2rq, 2rq+1, 2rq+8, 2rq+9}. Records read ONCE. sR/sx use pitch SRP=20
// floats so the 4 rq-lanes of a node always hit distinct banks (20r % 32
// cycles {0,8,16,24}/{20,28,4,12}), with 4-lane node-broadcast on top.
__global__ void __launch_bounds__(256)
k_node(const float* __restrict__ R, float* out) {
    int type  = blockIdx.y;
    int count = __ldg(&g_pos[type]);
    int base  = blockIdx.x * 64;
    if (base >= count) return;

    __shared__ float sR[NTYPES * 16 * SRP];   // 20480 B, padded rows
    __shared__ float sx[64 * SRP];            // 5120 B, padded x
    __shared__ float s_cf[NTYPES][64];        // 4096 B, transposed cf
    int tid = threadIdx.x;

    // stage R[type] padded: 4096 floats, 16 per thread (coalesced reads)
    {
        const float* Rb = R + (type << 12);
        #pragma unroll
        for (int k = 0; k < 16; k++) {
            int f = k * 256 + tid;             // 0..4095
            int tr = f >> 4, j = f & 15;       // tr = t*16 + r
            sR[tr * SRP + j] = __ldg(Rb + f);
        }
    }
    // stage records: 64 slots x 8 float4 = 512 float4, 2 per thread (coalesced)
    {
        const float4* recs = reinterpret_cast<const float4*>(
            g_rec + ((size_t)type * MAX_NODES + base) * 32);
        #pragma unroll
        for (int k = 0; k < 2; k++) {
            int f4 = k * 256 + tid;            // 0..511
            int slot = f4 >> 3, j4 = f4 & 7;
            float4 v = (base + slot < count) ? recs[f4] : make_float4(0,0,0,0);
            if (j4 < 4) {
                *reinterpret_cast<float4*>(sx + slot * SRP + j4 * 4) = v;  // 16B-aligned
            } else {
                int t0 = (j4 - 4) * 4;
                s_cf[t0+0][slot] = v.x; s_cf[t0+1][slot] = v.y;
                s_cf[t0+2][slot] = v.z; s_cf[t0+3][slot] = v.w;
            }
        }
    }
    __syncthreads();

    int node = tid >> 2, rq = tid & 3;
    int rA = 2*rq, rB = 2*rq + 1, rC = 2*rq + 8, rD = 2*rq + 9;

    // x into regs (conflict-free: node banks 20n%32 all distinct, 4-lane bcast)
    const float* xb = sx + node * SRP;
    float4 x0 = *reinterpret_cast<const float4*>(xb + 0);
    float4 x1 = *reinterpret_cast<const float4*>(xb + 4);
    float4 x2 = *reinterpret_cast<const float4*>(xb + 8);
    float4 x3 = *reinterpret_cast<const float4*>(xb + 12);

    float y0 = 0.0f, y1 = 0.0f, y2 = 0.0f, y3 = 0.0f;
    #pragma unroll 1
    for (int t = 0; t < NTYPES; t++) {         // outer NOT unrolled (I$)
        float c = s_cf[t][node];
        const float* Rt = sR + t * 16 * SRP;
        const float4* a = reinterpret_cast<const float4*>(Rt + rA * SRP);
        const float4* b = reinterpret_cast<const float4*>(Rt + rB * SRP);
        const float4* cc = reinterpret_cast<const float4*>(Rt + rC * SRP);
        const float4* dd = reinterpret_cast<const float4*>(Rt + rD * SRP);
        float4 a0=a[0],a1=a[1],a2=a[2],a3=a[3];
        float da = a0.x*x0.x + a0.y*x0.y + a0.z*x0.z + a0.w*x0.w
                 + a1.x*x1.x + a1.y*x1.y + a1.z*x1.z + a1.w*x1.w
                 + a2.x*x2.x + a2.y*x2.y + a2.z*x2.z + a2.w*x2.w
                 + a3.x*x3.x + a3.y*x3.y + a3.z*x3.z + a3.w*x3.w;
        float4 b0=b[0],b1=b[1],b2=b[2],b3=b[3];
        float db = b0.x*x0.x + b0.y*x0.y + b0.z*x0.z + b0.w*x0.w
                 + b1.x*x1.x + b1.y*x1.y + b1.z*x1.z + b1.w*x1.w
                 + b2.x*x2.x + b2.y*x2.y + b2.z*x2.z + b2.w*x2.w
                 + b3.x*x3.x + b3.y*x3.y + b3.z*x3.z + b3.w*x3.w;
        float4 c0=cc[0],c1=cc[1],c2=cc[2],c3=cc[3];
        float dc = c0.x*x0.x + c0.y*x0.y + c0.z*x0.z + c0.w*x0.w
                 + c1.x*x1.x + c1.y*x1.y + c1.z*x1.z + c1.w*x1.w
                 + c2.x*x2.x + c2.y*x2.y + c2.z*x2.z + c2.w*x2.w
                 + c3.x*x3.x + c3.y*x3.y + c3.z*x3.z + c3.w*x3.w;
        float4 d0=dd[0],d1=dd[1],d2=dd[2],d3=dd[3];
        float de = d0.x*x0.x + d0.y*x0.y + d0.z*x0.z + d0.w*x0.w
                 + d1.x*x1.x + d1.y*x1.y + d1.z*x1.z + d1.w*x1.w
                 + d2.x*x2.x + d2.y*x2.y + d2.z*x2.z + d2.w*x2.w
                 + d3.x*x3.x + d3.y*x3.y + d3.z*x3.z + d3.w*x3.w;
        y0 = fmaf(c, da, y0);
        y1 = fmaf(c, db, y1);
        y2 = fmaf(c, dc, y2);
        y3 = fmaf(c, de, y3);
    }
    float acc = y0*y0 + y1*y1 + y2*y2 + y3*y3;   // zero-staged slots contribute 0

    // block reduce -> one atomicAdd per block
    #pragma unroll
    for (int off = 16; off > 0; off >>= 1)
        acc += __shfl_down_sync(0xFFFFFFFFu, acc, off);
    __shared__ float warp_sums[8];
    int lane = tid & 31;
    int wid  = tid >> 5;
    if (lane == 0) warp_sums[wid] = acc;
    __syncthreads();
    if (wid == 0) {
        float s = (lane < 8) ? warp_sums[lane] : 0.0f;
        #pragma unroll
        for (int off = 4; off > 0; off >>= 1)
            s += __shfl_down_sync(0xFFu, s, off);
        if (lane == 0) atomicAdd(out, s);
    }
}

// ---------------------------------------------------------------- launch
extern "C" void kernel_launch(void* const* d_in, const int* in_sizes, int n_in,
                              void* d_out, int out_size) {
    const float* reps  = (const float*)d_in[0];  // [16, n_nodes]
    const float* rmaps = (const float*)d_in[1];  // [16,16,16,16]
    const int*   eidx  = (const int*)d_in[2];    // [2, n_edges]
    const int*   types = (const int*)d_in[3];    // [n_nodes]
    float* out = (float*)d_out;

    int n_nodes = in_sizes[3];
    if (n_nodes > MAX_NODES) n_nodes = MAX_NODES;
    int n_edges = in_sizes[2] / 2;
    const int* src = eidx;
    const int* dst = eidx + n_edges;

    const int T = 256;

    k_zero <<<(MAX_NODES * NTYPES / 4 + T - 1) / T, T>>>(out);
    k_count<<<(n_edges + T - 1) / T, T>>>(src, dst, types, n_edges);
    k_prep <<<(n_nodes + T - 1) / T, T>>>(reps, types, n_nodes);

    dim3 grid((n_nodes + 63) / 64, NTYPES);   // non-working blocks exit early
    k_node <<<grid, 256>>>(rmaps, out);
}

// round 16
// speedup vs baseline: 1.3173x; 1.3173x over previous
#include <cuda_runtime.h>
#include <cuda_bf16.h>
#include <math.h>

#define MAX_NODES 50000
#define D 16
#define NTYPES 16
#define RPB 4                         // rows per k_node block (grid.z = D/RPB)
#define TPT ((MAX_NODES + 255) / 256) // tiles per type = 196

// Scratch (allocation-free rule: __device__ globals)
__device__ int   g_cnt_out[MAX_NODES * NTYPES]; // out-edge type counts
__device__ int   g_cnt_in [MAX_NODES * NTYPES]; // in-edge type counts
__device__ int   g_pos[NTYPES];                 // bucket fill counters -> final counts
// Tile-SoA node records: [type][tile][j4 0..7][node 0..255][4]
//   j4 0..3 = normalized x, j4 4..7 = float net counts (out - in)
__device__ float g_rec[(size_t)NTYPES * TPT * 8 * 1024];

// ---------------------------------------------------------------- K0: zero counters + out
__global__ void k_zero(float* out) {
    int i = blockIdx.x * blockDim.x + threadIdx.x;
    int total4 = (MAX_NODES * NTYPES) / 4;
    if (i < total4) {
        reinterpret_cast<int4*>(g_cnt_out)[i] = make_int4(0, 0, 0, 0);
        reinterpret_cast<int4*>(g_cnt_in )[i] = make_int4(0, 0, 0, 0);
    }
    if (i < NTYPES) g_pos[i] = 0;
    if (i == 0) out[0] = 0.0f;
}

// ---------------------------------------------------------------- K1: per-edge type counts (2 atomics/edge)
__global__ void __launch_bounds__(256)
k_count(const int* __restrict__ src, const int* __restrict__ dst,
        const int* __restrict__ types, int n_edges) {
    int e = blockIdx.x * blockDim.x + threadIdx.x;
    if (e >= n_edges) return;
    int s  = src[e];
    int d  = dst[e];
    int ts = __ldg(types + s);
    int td = __ldg(types + d);
    atomicAdd(&g_cnt_out[s * NTYPES + td], 1);
    atomicAdd(&g_cnt_in [d * NTYPES + ts], 1);
}

// ---------------------------------------------------------------- K2: build tile-SoA type-sorted records
__global__ void __launch_bounds__(256)
k_prep(const float* __restrict__ reps, const int* __restrict__ types, int n_nodes) {
    __shared__ int s_hist[NTYPES], s_base[NTYPES];

    int tid  = threadIdx.x;
    int base = blockIdx.x * 256;
    int v    = base + tid;

    if (tid < NTYPES) s_hist[tid] = 0;
    __syncthreads();

    int t = 0, lrank = 0;
    float4 cf0, cf1, cf2, cf3;
    float inv = 0.0f;
    if (v < n_nodes) {
        t = __ldg(types + v);
        lrank = atomicAdd(&s_hist[t], 1);     // smem atomic
        const int4* co = reinterpret_cast<const int4*>(g_cnt_out + v * NTYPES);
        const int4* ci = reinterpret_cast<const int4*>(g_cnt_in  + v * NTYPES);
        int4 o0 = co[0], o1 = co[1], o2 = co[2], o3 = co[3];
        int4 i0 = ci[0], i1 = ci[1], i2 = ci[2], i3 = ci[3];
        int deg = i0.x+i0.y+i0.z+i0.w + i1.x+i1.y+i1.z+i1.w
                + i2.x+i2.y+i2.z+i2.w + i3.x+i3.y+i3.z+i3.w;
        inv = (deg > 0) ? rsqrtf((float)deg) : 0.0f;
        cf0 = make_float4((float)(o0.x-i0.x), (float)(o0.y-i0.y), (float)(o0.z-i0.z), (float)(o0.w-i0.w));
        cf1 = make_float4((float)(o1.x-i1.x), (float)(o1.y-i1.y), (float)(o1.z-i1.z), (float)(o1.w-i1.w));
        cf2 = make_float4((float)(o2.x-i2.x), (float)(o2.y-i2.y), (float)(o2.z-i2.z), (float)(o2.w-i2.w));
        cf3 = make_float4((float)(o3.x-i3.x), (float)(o3.y-i3.y), (float)(o3.z-i3.z), (float)(o3.w-i3.w));
    }
    __syncthreads();
    if (tid < NTYPES) s_base[tid] = atomicAdd(&g_pos[tid], s_hist[tid]);
    __syncthreads();

    if (v < n_nodes) {
        float x[D];
        #pragma unroll
        for (int i = 0; i < D; i++)
            x[i] = __ldg(reps + i * n_nodes + v) * inv;   // coalesced across warp

        int slot = s_base[t] + lrank;
        int tile = slot >> 8, off = slot & 255;
        float* tb = g_rec + ((size_t)(t * TPT + tile) * 8) * 1024;
        *reinterpret_cast<float4*>(tb + 0*1024 + off*4) = make_float4(x[0],  x[1],  x[2],  x[3]);
        *reinterpret_cast<float4*>(tb + 1*1024 + off*4) = make_float4(x[4],  x[5],  x[6],  x[7]);
        *reinterpret_cast<float4*>(tb + 2*1024 + off*4) = make_float4(x[8],  x[9],  x[10], x[11]);
        *reinterpret_cast<float4*>(tb + 3*1024 + off*4) = make_float4(x[12], x[13], x[14], x[15]);
        *reinterpret_cast<float4*>(tb + 4*1024 + off*4) = cf0;
        *reinterpret_cast<float4*>(tb + 5*1024 + off*4) = cf1;
        *reinterpret_cast<float4*>(tb + 6*1024 + off*4) = cf2;
        *reinterpret_cast<float4*>(tb + 7*1024 + off*4) = cf3;
    }
}

// ---------------------------------------------------------------- K3: weighted matvec + sum of squares
// Block = ONE (type, tile, row-slice). Thread = node: all R reads are
// full-warp-uniform smem broadcasts (the only LDS pattern measured cheap:
// R15's intra-warp row split multi-phased every LDS.128). cf in TRANSPOSED
// smem [t][node] (conflict-free; the CFPAD=20 per-thread layout had
// gcd(20,32)=4 -> 4-way conflicts). Record loads coalesced (tile-SoA).
__global__ void __launch_bounds__(256, 4)
k_node(const float* __restrict__ R, float* out) {
    int type  = blockIdx.y;
    int count = __ldg(&g_pos[type]);
    int base  = blockIdx.x * 256;
    if (base >= count) return;
    int ro = blockIdx.z * RPB;

    __shared__ float sR[NTYPES * RPB * 16];      // 4 KB: rows ro..ro+3 of R[type][t]
    __shared__ float s_cf[NTYPES][256];          // 16 KB, transposed: [t][node]
    int tid = threadIdx.x;
    {
        int w = tid;                              // 256 float4 entries
        int t = w >> 4, r = (w >> 2) & 3, j4 = w & 3;
        const float4* src = reinterpret_cast<const float4*>(R)
                          + (type << 10) + (t << 6) + ((ro + r) << 2) + j4;
        reinterpret_cast<float4*>(sR)[w] = *src;
    }

    const float* tb = g_rec + ((size_t)(type * TPT + blockIdx.x) * 8) * 1024;
    // coalesced LDG.128: lanes read consecutive 16B
    float4 x0 = *reinterpret_cast<const float4*>(tb + 0*1024 + tid*4);
    float4 x1 = *reinterpret_cast<const float4*>(tb + 1*1024 + tid*4);
    float4 x2 = *reinterpret_cast<const float4*>(tb + 2*1024 + tid*4);
    float4 x3 = *reinterpret_cast<const float4*>(tb + 3*1024 + tid*4);
    #pragma unroll
    for (int j4 = 0; j4 < 4; j4++) {             // conflict-free transposed STS
        float4 c = *reinterpret_cast<const float4*>(tb + (4+j4)*1024 + tid*4);
        s_cf[j4*4+0][tid] = c.x; s_cf[j4*4+1][tid] = c.y;
        s_cf[j4*4+2][tid] = c.z; s_cf[j4*4+3][tid] = c.w;
    }
    __syncthreads();

    int idx = base + tid;
    float acc = 0.0f;
    if (idx < count) {
        float y0 = 0.0f, y1 = 0.0f, y2 = 0.0f, y3 = 0.0f;
        #pragma unroll 1
        for (int t = 0; t < NTYPES; t++) {       // outer NOT unrolled (I$)
            float c = s_cf[t][tid];              // conflict-free: lanes consecutive
            const float4* rb = reinterpret_cast<const float4*>(sR + t * (RPB*16));
            #pragma unroll
            for (int r = 0; r < RPB; r++) {
                float4 r0 = rb[r*4+0], r1 = rb[r*4+1], r2 = rb[r*4+2], r3 = rb[r*4+3];
                float dotv = r0.x*x0.x + r0.y*x0.y + r0.z*x0.z + r0.w*x0.w
                           + r1.x*x1.x + r1.y*x1.y + r1.z*x1.z + r1.w*x1.w
                           + r2.x*x2.x + r2.y*x2.y + r2.z*x2.z + r2.w*x2.w
                           + r3.x*x3.x + r3.y*x3.y + r3.z*x3.z + r3.w*x3.w;
                if (r == 0) y0 = fmaf(c, dotv, y0);
                if (r == 1) y1 = fmaf(c, dotv, y1);
                if (r == 2) y2 = fmaf(c, dotv, y2);
                if (r == 3) y3 = fmaf(c, dotv, y3);
            }
        }
        acc = y0*y0 + y1*y1 + y2*y2 + y3*y3;
    }

    // block reduce -> one atomicAdd per block
    #pragma unroll
    for (int off = 16; off > 0; off >>= 1)
        acc += __shfl_down_sync(0xFFFFFFFFu, acc, off);
    __shared__ float warp_sums[8];
    int lane = tid & 31;
    int wid  = tid >> 5;
    if (lane == 0) warp_sums[wid] = acc;
    __syncthreads();
    if (wid == 0) {
        float s = (lane < 8) ? warp_sums[lane] : 0.0f;
        #pragma unroll
        for (int off = 4; off > 0; off >>= 1)
            s += __shfl_down_sync(0xFFu, s, off);
        if (lane == 0) atomicAdd(out, s);
    }
}

// ---------------------------------------------------------------- launch
extern "C" void kernel_launch(void* const* d_in, const int* in_sizes, int n_in,
                              void* d_out, int out_size) {
    const float* reps  = (const float*)d_in[0];  // [16, n_nodes]
    const float* rmaps = (const float*)d_in[1];  // [16,16,16,16]
    const int*   eidx  = (const int*)d_in[2];    // [2, n_edges]
    const int*   types = (const int*)d_in[3];    // [n_nodes]
    float* out = (float*)d_out;

    int n_nodes = in_sizes[3];
    if (n_nodes > MAX_NODES) n_nodes = MAX_NODES;
    int n_edges = in_sizes[2] / 2;
    const int* src = eidx;
    const int* dst = eidx + n_edges;

    const int T = 256;

    k_zero <<<(MAX_NODES * NTYPES / 4 + T - 1) / T, T>>>(out);
    k_count<<<(n_edges + T - 1) / T, T>>>(src, dst, types, n_edges);
    k_prep <<<(n_nodes + T - 1) / T, T>>>(reps, types, n_nodes);

    dim3 grid(TPT, NTYPES, D / RPB);   // non-working blocks exit early
    k_node <<<grid, 256>>>(rmaps, out);
}